// round 9
// baseline (speedup 1.0000x reference)
#include <cuda_runtime.h>
#include <cuda_bf16.h>

// Problem shape (fixed)
#define BB 16
#define TT 4096
#define HH 512
#define H4 128             // float4 per row
#define LANES 4            // float4 lanes per CTA -> 16 float columns
#define SLICES 32          // 32 slices x 16 cols = 512 = H
#define THALF 2048
#define TROWS 32
#define ITERS (THALF / TROWS)   // 64 iterations per thread
#define THREADS 128
#define NPAIR (BB * SLICES)     // 512
#define NCTA (NPAIR * 2)        // 1024

// Per-CTA partial: [0..3]=global float4x4, [4..7]=local, [8].x=count (as int bits)
__device__ float4 g_pair[NCTA][9];       // 144 KB
__device__ int    g_flag[NPAIR];         // zero-init; combiner resets -> replayable

__global__ __launch_bounds__(THREADS) void pool_kernel(
    const float4* __restrict__ x,
    const int* __restrict__ lengths,
    const int* __restrict__ mask,        // jax bool materialized as int32
    float* __restrict__ out)
{
    const int blk   = blockIdx.x;        // = pair*2 + half
    const int b     = blk >> 6;          // / (SLICES*2)
    const int slice = (blk >> 1) & (SLICES - 1);
    const int half  = blk & 1;
    const int pair  = blk >> 1;

    const int tid  = threadIdx.x;
    const int lane = tid & (LANES - 1);  // float4 column within slice
    const int trow = tid >> 2;           // 0..31

    const int L  = lengths[b];
    const int t0 = half * THALF;

    const float4* __restrict__ xp =
        x + (size_t)b * TT * H4 + (size_t)t0 * H4 + slice * LANES + lane;
    const int* __restrict__ mp = mask + (size_t)b * TT + t0;

    float4 ag = make_float4(0.f, 0.f, 0.f, 0.f);
    float4 al = make_float4(0.f, 0.f, 0.f, 0.f);
    int cnt = 0;

    // Walk this half's 2048 rows, 32 at a time. Rows needed by neither view
    // are never fetched (uniform across the 4-lane group).
    #pragma unroll 8
    for (int k = 0; k < ITERS; ++k) {
        const int t = trow + k * TROWS;
        const bool g = (t0 + t) < L;
        const int  m = mp[t];
        if (g || m) {
            float4 v = __ldcs(&xp[(size_t)t * H4]);
            if (g) { ag.x += v.x; ag.y += v.y; ag.z += v.z; ag.w += v.w; }
            if (m) { al.x += v.x; al.y += v.y; al.z += v.z; al.w += v.w;
                     cnt += (lane == 0); }
        }
    }

    // Tree-reduce across the 32 t-rows (per lane).
    __shared__ float4 s_g[THREADS], s_l[THREADS];
    __shared__ int    s_c[THREADS];
    __shared__ int    s_v;
    s_g[tid] = ag; s_l[tid] = al; s_c[tid] = cnt;
    __syncthreads();

    #pragma unroll
    for (int st = TROWS / 2; st >= 1; st >>= 1) {
        if (trow < st) {
            const int o = tid + st * LANES;
            float4 a = s_g[o], d = s_l[o];
            float4 sg = s_g[tid], sl = s_l[tid];
            sg.x += a.x; sg.y += a.y; sg.z += a.z; sg.w += a.w;
            sl.x += d.x; sl.y += d.y; sl.z += d.z; sl.w += d.w;
            s_g[tid] = sg; s_l[tid] = sl;
            s_c[tid] += s_c[o];
        }
        __syncthreads();
    }

    // Publish this half's partial (tid 0..3 hold the 4 float4 columns).
    if (tid < LANES) {
        g_pair[blk][lane]     = s_g[lane];
        g_pair[blk][4 + lane] = s_l[lane];
        if (lane == 0)
            g_pair[blk][8] = make_float4(__int_as_float(s_c[0]), 0.f, 0.f, 0.f);
    }
    __threadfence();                     // release partial before flag
    __syncthreads();
    if (tid == 0) s_v = atomicAdd(&g_flag[pair], 1);
    __syncthreads();
    if (s_v == 0) return;                // first arriver: done

    // Second arriver combines both halves and writes the output.
    __threadfence();                     // acquire partner's partial
    if (tid < LANES) {
        const int pblk = blk ^ 1;
        float4 pag = g_pair[pblk][lane];
        float4 pal = g_pair[pblk][4 + lane];
        const int pcnt = __float_as_int(g_pair[pblk][8].x);
        const int tot  = s_c[0] + pcnt;

        const float dg = 1.0f / (float)(L   > 1 ? L   : 1);
        const float dl = 1.0f / (float)(tot > 1 ? tot : 1);

        float4 og = s_g[lane], ol = s_l[lane];
        og.x = (og.x + pag.x) * dg; og.y = (og.y + pag.y) * dg;
        og.z = (og.z + pag.z) * dg; og.w = (og.w + pag.w) * dg;
        ol.x = (ol.x + pal.x) * dl; ol.y = (ol.y + pal.y) * dl;
        ol.z = (ol.z + pal.z) * dl; ol.w = (ol.w + pal.w) * dl;

        float4* o4 = reinterpret_cast<float4*>(out)
                   + (size_t)b * (2 * HH / 4) + slice * LANES + lane;
        o4[0]  = og;
        o4[H4] = ol;

        if (lane == 0) g_flag[pair] = 0;   // reset for next graph replay
    }
}

extern "C" void kernel_launch(void* const* d_in, const int* in_sizes, int n_in,
                              void* d_out, int out_size)
{
    const float4* x       = (const float4*)d_in[0];   // [B,T,H] f32
    const int*    lengths = (const int*)d_in[1];      // [B] i32
    const int*    mask    = (const int*)d_in[2];      // [B,T] bool -> i32
    float*        out     = (float*)d_out;            // [B, 2H] f32

    pool_kernel<<<NCTA, THREADS>>>(x, lengths, mask, out);
}

// round 10
// speedup vs baseline: 2.1558x; 2.1558x over previous
#include <cuda_runtime.h>
#include <cuda_bf16.h>

// Problem shape (fixed by the reference)
#define BB 16
#define TT 4096
#define HH 512
#define SS 64            // T-chunks per batch
#define TC (TT / SS)     // 64 rows per chunk
#define H4 (HH / 4)      // 128 float4 per row
#define CP 16            // pass-2 chunk-splits  (SS/CP = 4 chunks per thread)
#define COLP 2           // pass-2 column-splits (each CTA: 128 float4-cols)

// Scratch: per (b, chunk): 512 global-sum + 512 local-sum floats (4 MiB)
__device__ float g_partial[BB * SS * 2 * HH];
__device__ int   g_counts[BB * SS];

// Pass 1: each CTA handles one (b, t-chunk); 128 threads x float4 cover H=512.
// Rows with t >= L AND mask==0 are never fetched (warp-uniform skip, ~25%
// traffic cut). First 32 CTAs also zero the output for pass-2's atomics.
__global__ __launch_bounds__(128) void pass1_kernel(
    const float4* __restrict__ x,
    const int* __restrict__ lengths,
    const int* __restrict__ mask,        // jax bool materialized as int32
    float4* __restrict__ out4)           // [B*2H/4] — zeroed here
{
    const int blk = blockIdx.x;          // 0 .. B*S-1
    const int b   = blk / SS;
    const int s   = blk % SS;
    const int tid = threadIdx.x;         // 0..127

    if (blk < 32) out4[blk * 128 + tid] = make_float4(0.f, 0.f, 0.f, 0.f);

    const int L  = lengths[b];
    const int t0 = s * TC;
    int Lc = L - t0;
    Lc = Lc < 0 ? 0 : (Lc > TC ? TC : Lc);

    const float4* __restrict__ xp = x + (size_t)b * TT * H4 + (size_t)t0 * H4 + tid;
    const int* __restrict__ mp = mask + (size_t)b * TT + t0;

    float4 ag = make_float4(0.f, 0.f, 0.f, 0.f);
    float4 al = make_float4(0.f, 0.f, 0.f, 0.f);
    int cnt = 0;

    // Region A: t < Lc — row always fetched; mask gates the local sum.
    int t = 0;
    #pragma unroll 8
    for (; t < Lc; ++t) {
        float4 v = xp[(size_t)t * H4];
        ag.x += v.x; ag.y += v.y; ag.z += v.z; ag.w += v.w;
        if (mp[t] != 0) { al.x += v.x; al.y += v.y; al.z += v.z; al.w += v.w; cnt++; }
    }
    // Region B: t >= Lc — fetch only masked rows.
    #pragma unroll 4
    for (; t < TC; ++t) {
        if (mp[t] != 0) {
            float4 v = xp[(size_t)t * H4];
            al.x += v.x; al.y += v.y; al.z += v.z; al.w += v.w; cnt++;
        }
    }

    float4* outp = reinterpret_cast<float4*>(g_partial) + (size_t)blk * (2 * HH / 4);
    outp[tid]      = ag;
    outp[H4 + tid] = al;
    if (tid == 0) g_counts[blk] = cnt;
}

// Pass 2: 512 CTAs = (b, colpart, chunkpart); 128 threads. float4 partial
// loads (4 chunks/thread), per-CTA count reduce (smem tree, only for the
// local-half CTAs), pre-divide, 4 scalar atomicAdds into out.
__global__ __launch_bounds__(128) void pass2_kernel(
    const int* __restrict__ lengths,
    float* __restrict__ out)
{
    const int blk       = blockIdx.x;
    const int b         = blk / (COLP * CP);
    const int colpart   = (blk / CP) % COLP;   // 0: global half, 1: local half
    const int chunkpart = blk % CP;
    const int tid       = threadIdx.x;
    const int fc        = colpart * 128 + tid; // float4-column in [0, 256)

    __shared__ int s_cnt[64];
    __shared__ float s_inv;

    if (colpart == 1) {
        if (tid < 64) s_cnt[tid] = g_counts[b * SS + tid];
        __syncthreads();
        if (tid < 16) s_cnt[tid] += s_cnt[tid + 16] + s_cnt[tid + 32] + s_cnt[tid + 48];
        __syncthreads();
        if (tid == 0) {
            int tot = 0;
            #pragma unroll
            for (int i = 0; i < 16; ++i) tot += s_cnt[i];
            s_inv = 1.0f / (float)(tot > 1 ? tot : 1);
        }
        __syncthreads();
    } else {
        const int L = lengths[b];
        if (tid == 0) s_inv = 1.0f / (float)(L > 1 ? L : 1);
        __syncthreads();
    }
    const float inv = s_inv;

    const int c0 = chunkpart * (SS / CP);
    const float4* p = reinterpret_cast<const float4*>(g_partial)
                    + ((size_t)b * SS + c0) * (2 * HH / 4) + fc;

    float4 acc = make_float4(0.f, 0.f, 0.f, 0.f);
    #pragma unroll
    for (int c = 0; c < SS / CP; ++c) {
        float4 v = p[(size_t)c * (2 * HH / 4)];
        acc.x += v.x; acc.y += v.y; acc.z += v.z; acc.w += v.w;
    }

    float* o = out + (size_t)b * 2 * HH + 4 * fc;
    atomicAdd(&o[0], acc.x * inv);
    atomicAdd(&o[1], acc.y * inv);
    atomicAdd(&o[2], acc.z * inv);
    atomicAdd(&o[3], acc.w * inv);
}

extern "C" void kernel_launch(void* const* d_in, const int* in_sizes, int n_in,
                              void* d_out, int out_size)
{
    const float4* x       = (const float4*)d_in[0];   // [B,T,H] f32
    const int*    lengths = (const int*)d_in[1];      // [B] i32
    const int*    mask    = (const int*)d_in[2];      // [B,T] bool -> i32
    float*        out     = (float*)d_out;            // [B, 2H] f32

    pass1_kernel<<<BB * SS, 128>>>(x, lengths, mask, (float4*)out);
    pass2_kernel<<<BB * COLP * CP, 128>>>(lengths, out);
}